// round 5
// baseline (speedup 1.0000x reference)
#include <cuda_runtime.h>
#include <cstdint>

#define NN 50000
#define NE 25000
#define CC 128

// ---- scratch (device globals; no allocation) ----
__device__ __align__(16) float g_esum[NE * CC];   // per-edge sum of gathered x
__device__ __align__(16) float g_t[NE * CC];      // relu(mean @ W1^T + b1)
__device__ __align__(16) float g_e2[NE * CC];     // t @ W2^T + b2
__device__ __align__(16) float g_cnt_e[NE];
__device__ __align__(16) float g_cnt_n[NN];
__device__ __align__(16) float g_WT1[CC * CC];    // W1 transposed: [k][n]
__device__ __align__(16) float g_WT2[CC * CC];    // W2 transposed: [k][n]

// ---- zero accumulators (incl. d_out, which is poisoned) + transpose weights ----
__global__ void prep_kernel(float* __restrict__ out,
                            const float* __restrict__ W1,
                            const float* __restrict__ W2) {
    int tid = blockIdx.x * blockDim.x + threadIdx.x;
    int stride = gridDim.x * blockDim.x;
    float4 z = make_float4(0.f, 0.f, 0.f, 0.f);
    float4* p1 = reinterpret_cast<float4*>(g_esum);
    for (int i = tid; i < NE * CC / 4; i += stride) p1[i] = z;
    float4* p2 = reinterpret_cast<float4*>(out);
    for (int i = tid; i < NN * CC / 4; i += stride) p2[i] = z;
    float4* p3 = reinterpret_cast<float4*>(g_cnt_e);
    for (int i = tid; i < NE / 4; i += stride) p3[i] = z;
    float4* p4 = reinterpret_cast<float4*>(g_cnt_n);
    for (int i = tid; i < NN / 4; i += stride) p4[i] = z;
    for (int i = tid; i < CC * CC; i += stride) {
        int n = i >> 7;
        int k = i & 127;
        g_WT1[k * CC + n] = W1[i];
        g_WT2[k * CC + n] = W2[i];
    }
}

// ---- scatter1: x[node] -> esum[edge] via vector reductions; counts too ----
__global__ void scatter1_kernel(const float* __restrict__ x,
                                const int* __restrict__ nidx,
                                const int* __restrict__ eidx, int ninc) {
    int gw = (blockIdx.x * blockDim.x + threadIdx.x) >> 5;
    int lane = threadIdx.x & 31;
    if (gw >= ninc) return;
    int n = __ldg(nidx + gw);
    int e = __ldg(eidx + gw);
    float4 v = *reinterpret_cast<const float4*>(x + (size_t)n * CC + lane * 4);
    float* dst = g_esum + (size_t)e * CC + lane * 4;
    asm volatile("red.global.add.v4.f32 [%0], {%1,%2,%3,%4};"
                 :: "l"(dst), "f"(v.x), "f"(v.y), "f"(v.z), "f"(v.w)
                 : "memory");
    if (lane == 0) {
        atomicAdd(g_cnt_e + e, 1.0f);
        atomicAdd(g_cnt_n + n, 1.0f);
    }
}

// ---- scatter2: e2[edge] -> out[node] ----
__global__ void scatter2_kernel(const int* __restrict__ nidx,
                                const int* __restrict__ eidx,
                                float* __restrict__ out, int ninc) {
    int gw = (blockIdx.x * blockDim.x + threadIdx.x) >> 5;
    int lane = threadIdx.x & 31;
    if (gw >= ninc) return;
    int n = __ldg(nidx + gw);
    int e = __ldg(eidx + gw);
    float4 v = *reinterpret_cast<const float4*>(g_e2 + (size_t)e * CC + lane * 4);
    float* dst = out + (size_t)n * CC + lane * 4;
    asm volatile("red.global.add.v4.f32 [%0], {%1,%2,%3,%4};"
                 :: "l"(dst), "f"(v.x), "f"(v.y), "f"(v.z), "f"(v.w)
                 : "memory");
}

// ---- fused GEMM: out = [relu]( [A/cnt] @ W^T + bias ), 128x128 tile, 8x8 micro ----
// STAGE 0: A=g_esum (scaled by 1/cnt_e), W=g_WT1, out=g_t, relu
// STAGE 1: A=g_t, W=g_WT2, out=g_e2, no relu
template <int STAGE>
__global__ void __launch_bounds__(256, 2) gemm_kernel(const float* __restrict__ bias) {
    const float* __restrict__ A  = (STAGE == 0) ? g_esum : g_t;
    const float* __restrict__ WT = (STAGE == 0) ? g_WT1 : g_WT2;
    float* __restrict__ out      = (STAGE == 0) ? g_t : g_e2;
    constexpr bool MEAN = (STAGE == 0);
    constexpr bool RELU = (STAGE == 0);
    const int M = NE;
    constexpr int BK = 16;
    constexpr int APAD = 132;   // 132*4 % 16 == 0 -> float4-aligned rows

    __shared__ __align__(16) float As[2][BK][APAD];  // [k][m]
    __shared__ __align__(16) float Bs[2][BK][128];   // [k][n]

    const int tid = threadIdx.x;
    const int tx = tid & 15;    // n-dir: 8 cols each
    const int ty = tid >> 4;    // m-dir: 8 rows each
    const int row0 = blockIdx.x * 128;

    // A loader: 128 rows x 4 float4-cols = 512 float4; 2 per thread
    const int ar  = tid >> 2;   // 0..63, rows ar and ar+64
    const int ac4 = tid & 3;    // float4 col within BK=16
    // B loader: 16 rows x 32 float4 = 512 float4; 2 per thread
    float acc[8][8];
#pragma unroll
    for (int i = 0; i < 8; i++)
#pragma unroll
        for (int j = 0; j < 8; j++) acc[i][j] = 0.f;

    float bias_r[8];
#pragma unroll
    for (int j = 0; j < 8; j++) bias_r[j] = __ldg(bias + tx * 8 + j);

    float4 ra[2], rb[2];

    // scale factors for the 2 A-rows this thread loads (MEAN stage only)
    float ascale[2] = {1.f, 1.f};
    if (MEAN) {
#pragma unroll
        for (int p = 0; p < 2; p++) {
            int gm = row0 + ar + p * 64;
            if (gm < M) ascale[p] = 1.f / fmaxf(__ldg(g_cnt_e + gm), 1.f);
        }
    }

    auto ldg_chunk = [&](int kb) {
#pragma unroll
        for (int p = 0; p < 2; p++) {
            int gm = row0 + ar + p * 64;
            float4 v = make_float4(0.f, 0.f, 0.f, 0.f);
            if (gm < M)
                v = *reinterpret_cast<const float4*>(A + (size_t)gm * CC + kb + ac4 * 4);
            if (MEAN) { v.x *= ascale[p]; v.y *= ascale[p]; v.z *= ascale[p]; v.w *= ascale[p]; }
            ra[p] = v;
        }
#pragma unroll
        for (int p = 0; p < 2; p++) {
            int idx = tid + p * 256;
            int kr = idx >> 5;
            int c4 = idx & 31;
            rb[p] = *reinterpret_cast<const float4*>(WT + (size_t)(kb + kr) * CC + c4 * 4);
        }
    };
    auto sts_chunk = [&](int buf) {
#pragma unroll
        for (int p = 0; p < 2; p++) {
            int r = ar + p * 64;
            As[buf][ac4 * 4 + 0][r] = ra[p].x;
            As[buf][ac4 * 4 + 1][r] = ra[p].y;
            As[buf][ac4 * 4 + 2][r] = ra[p].z;
            As[buf][ac4 * 4 + 3][r] = ra[p].w;
        }
#pragma unroll
        for (int p = 0; p < 2; p++) {
            int idx = tid + p * 256;
            int kr = idx >> 5;
            int c4 = idx & 31;
            *reinterpret_cast<float4*>(&Bs[buf][kr][c4 * 4]) = rb[p];
        }
    };

    ldg_chunk(0);
    sts_chunk(0);
    __syncthreads();

    constexpr int NCHUNK = CC / BK;  // 8
#pragma unroll
    for (int c = 0; c < NCHUNK; c++) {
        int buf = c & 1;
        if (c < NCHUNK - 1) ldg_chunk((c + 1) * BK);
#pragma unroll
        for (int k = 0; k < BK; k++) {
            float4 a0 = *reinterpret_cast<float4*>(&As[buf][k][ty * 8]);
            float4 a1 = *reinterpret_cast<float4*>(&As[buf][k][ty * 8 + 4]);
            float4 b0 = *reinterpret_cast<float4*>(&Bs[buf][k][tx * 8]);
            float4 b1 = *reinterpret_cast<float4*>(&Bs[buf][k][tx * 8 + 4]);
            float a[8] = {a0.x, a0.y, a0.z, a0.w, a1.x, a1.y, a1.z, a1.w};
            float b[8] = {b0.x, b0.y, b0.z, b0.w, b1.x, b1.y, b1.z, b1.w};
#pragma unroll
            for (int i = 0; i < 8; i++)
#pragma unroll
                for (int j = 0; j < 8; j++) acc[i][j] += a[i] * b[j];
        }
        if (c < NCHUNK - 1) {
            sts_chunk(buf ^ 1);
            __syncthreads();
        }
    }

    // ---- epilogue: float4 stores ----
#pragma unroll
    for (int i = 0; i < 8; i++) {
        int gm = row0 + ty * 8 + i;
        if (gm < M) {
            float v0[4], v1[4];
#pragma unroll
            for (int j = 0; j < 4; j++) {
                float v = acc[i][j] + bias_r[j];
                v0[j] = RELU ? fmaxf(v, 0.f) : v;
            }
#pragma unroll
            for (int j = 0; j < 4; j++) {
                float v = acc[i][4 + j] + bias_r[4 + j];
                v1[j] = RELU ? fmaxf(v, 0.f) : v;
            }
            float4* o = reinterpret_cast<float4*>(out + (size_t)gm * CC + tx * 8);
            o[0] = make_float4(v0[0], v0[1], v0[2], v0[3]);
            o[1] = make_float4(v1[0], v1[1], v1[2], v1[3]);
        }
    }
}

// ---- finalize: out = relu(out / max(cnt_n, 1)) ----
__global__ void finalize_kernel(float* __restrict__ out) {
    int i = blockIdx.x * blockDim.x + threadIdx.x;
    int stride = gridDim.x * blockDim.x;
    float4* p = reinterpret_cast<float4*>(out);
    for (; i < NN * CC / 4; i += stride) {
        int m = i >> 5;  // 32 float4 per row
        float s = 1.f / fmaxf(g_cnt_n[m], 1.f);
        float4 v = p[i];
        v.x = fmaxf(v.x * s, 0.f);
        v.y = fmaxf(v.y * s, 0.f);
        v.z = fmaxf(v.z * s, 0.f);
        v.w = fmaxf(v.w * s, 0.f);
        p[i] = v;
    }
}

extern "C" void kernel_launch(void* const* d_in, const int* in_sizes, int n_in,
                              void* d_out, int out_size) {
    const float* x  = (const float*)d_in[0];
    const int*   hi = (const int*)d_in[1];
    const float* W1 = (const float*)d_in[2];
    const float* b1 = (const float*)d_in[3];
    const float* W2 = (const float*)d_in[4];
    const float* b2 = (const float*)d_in[5];
    float* out = (float*)d_out;

    int ninc = in_sizes[1] / 2;
    const int* nidx = hi;          // hyperedge_index[0]
    const int* eidx = hi + ninc;   // hyperedge_index[1]

    prep_kernel<<<1024, 256>>>(out, W1, W2);
    scatter1_kernel<<<(ninc + 7) / 8, 256>>>(x, nidx, eidx, ninc);
    gemm_kernel<0><<<(NE + 127) / 128, 256>>>(b1);
    gemm_kernel<1><<<(NE + 127) / 128, 256>>>(b2);
    scatter2_kernel<<<(ninc + 7) / 8, 256>>>(nidx, eidx, out, ninc);
    finalize_kernel<<<1024, 256>>>(out);
}

// round 6
// speedup vs baseline: 1.1004x; 1.1004x over previous
#include <cuda_runtime.h>
#include <cstdint>

#define NN 50000
#define NE 25000
#define CC 128

// ---- scratch (device globals; no allocation) ----
__device__ __align__(16) float g_esum[NE * CC];   // per-edge sum of gathered x
__device__ __align__(16) float g_t[NE * CC];      // relu(mean @ W1^T + b1)
__device__ __align__(16) float g_e2[NE * CC];     // t @ W2^T + b2
__device__ __align__(16) float g_cnt_e[NE];
__device__ __align__(16) float g_cnt_n[NN];
__device__ __align__(16) float g_WT1[CC * CC];    // W1 transposed: [k][n]
__device__ __align__(16) float g_WT2[CC * CC];    // W2 transposed: [k][n]

// ---- zero accumulators (incl. d_out, which is poisoned) + transpose weights ----
__global__ void prep_kernel(float* __restrict__ out,
                            const float* __restrict__ W1,
                            const float* __restrict__ W2) {
    int tid = blockIdx.x * blockDim.x + threadIdx.x;
    int stride = gridDim.x * blockDim.x;
    float4 z = make_float4(0.f, 0.f, 0.f, 0.f);
    float4* p1 = reinterpret_cast<float4*>(g_esum);
    for (int i = tid; i < NE * CC / 4; i += stride) p1[i] = z;
    float4* p2 = reinterpret_cast<float4*>(out);
    for (int i = tid; i < NN * CC / 4; i += stride) p2[i] = z;
    float4* p3 = reinterpret_cast<float4*>(g_cnt_e);
    for (int i = tid; i < NE / 4; i += stride) p3[i] = z;
    float4* p4 = reinterpret_cast<float4*>(g_cnt_n);
    for (int i = tid; i < NN / 4; i += stride) p4[i] = z;
    for (int i = tid; i < CC * CC; i += stride) {
        int n = i >> 7;
        int k = i & 127;
        g_WT1[k * CC + n] = W1[i];
        g_WT2[k * CC + n] = W2[i];
    }
}

// ---- scatter1: x[node] -> esum[edge] via vector reductions; counts too ----
__global__ void scatter1_kernel(const float* __restrict__ x,
                                const int* __restrict__ nidx,
                                const int* __restrict__ eidx, int ninc) {
    int gw = (blockIdx.x * blockDim.x + threadIdx.x) >> 5;
    int lane = threadIdx.x & 31;
    if (gw >= ninc) return;
    int n = __ldg(nidx + gw);
    int e = __ldg(eidx + gw);
    float4 v = *reinterpret_cast<const float4*>(x + (size_t)n * CC + lane * 4);
    float* dst = g_esum + (size_t)e * CC + lane * 4;
    asm volatile("red.global.add.v4.f32 [%0], {%1,%2,%3,%4};"
                 :: "l"(dst), "f"(v.x), "f"(v.y), "f"(v.z), "f"(v.w)
                 : "memory");
    if (lane == 0) {
        atomicAdd(g_cnt_e + e, 1.0f);
        atomicAdd(g_cnt_n + n, 1.0f);
    }
}

// ---- scatter2: e2[edge] -> out[node] ----
__global__ void scatter2_kernel(const int* __restrict__ nidx,
                                const int* __restrict__ eidx,
                                float* __restrict__ out, int ninc) {
    int gw = (blockIdx.x * blockDim.x + threadIdx.x) >> 5;
    int lane = threadIdx.x & 31;
    if (gw >= ninc) return;
    int n = __ldg(nidx + gw);
    int e = __ldg(eidx + gw);
    float4 v = *reinterpret_cast<const float4*>(g_e2 + (size_t)e * CC + lane * 4);
    float* dst = out + (size_t)n * CC + lane * 4;
    asm volatile("red.global.add.v4.f32 [%0], {%1,%2,%3,%4};"
                 :: "l"(dst), "f"(v.x), "f"(v.y), "f"(v.z), "f"(v.w)
                 : "memory");
}

// ---- fused GEMM: out = [relu]( [A/cnt] @ W^T + bias ), 64x128 tile, 4x8 micro ----
// STAGE 0: A=g_esum (scaled by 1/cnt_e), W=g_WT1, out=g_t, relu
// STAGE 1: A=g_t, W=g_WT2, out=g_e2, no relu
template <int STAGE>
__global__ void __launch_bounds__(256) gemm_kernel(const float* __restrict__ bias) {
    const float* __restrict__ A  = (STAGE == 0) ? g_esum : g_t;
    const float* __restrict__ WT = (STAGE == 0) ? g_WT1 : g_WT2;
    float* __restrict__ out      = (STAGE == 0) ? g_t : g_e2;
    constexpr bool MEAN = (STAGE == 0);
    constexpr bool RELU = (STAGE == 0);
    const int M = NE;
    constexpr int APAD = 68;   // 68*4 = 272B row stride, 16B-aligned

    __shared__ __align__(16) float As[32][APAD];   // [k][m]
    __shared__ __align__(16) float Bs[32][128];    // [k][n]

    const int tid = threadIdx.x;
    const int ty = tid >> 4;   // 0..15 -> 4 rows each
    const int tx = tid & 15;   // 0..15 -> 8 cols each
    const int row0 = blockIdx.x * 64;

    float acc[4][8];
#pragma unroll
    for (int i = 0; i < 4; i++)
#pragma unroll
        for (int j = 0; j < 8; j++) acc[i][j] = 0.f;

    float bias_r[8];
#pragma unroll
    for (int j = 0; j < 8; j++) bias_r[j] = __ldg(bias + tx * 8 + j);

    // A loader: 64 rows x 8 float4 = 512 float4; 2 per thread
    const int ar  = tid >> 3;   // 0..31, rows ar and ar+32
    const int akq = tid & 7;    // float4 slot within 32-wide k chunk
    // B loader: 32 rows x 32 float4 = 1024 float4; 4 per thread
    const int bk  = tid >> 3;   // 0..31
    const int bnq = tid & 7;    // 0..7

    float ascale[2] = {1.f, 1.f};
    if (MEAN) {
#pragma unroll
        for (int p = 0; p < 2; p++) {
            int gm = row0 + ar + p * 32;
            if (gm < M) ascale[p] = 1.f / fmaxf(__ldg(g_cnt_e + gm), 1.f);
        }
    }

    float4 ra[2], rb[4];
    auto ldg_chunk = [&](int kb) {
#pragma unroll
        for (int p = 0; p < 2; p++) {
            int gm = row0 + ar + p * 32;
            float4 v = make_float4(0.f, 0.f, 0.f, 0.f);
            if (gm < M)
                v = *reinterpret_cast<const float4*>(A + (size_t)gm * CC + kb + akq * 4);
            if (MEAN) { v.x *= ascale[p]; v.y *= ascale[p]; v.z *= ascale[p]; v.w *= ascale[p]; }
            ra[p] = v;
        }
#pragma unroll
        for (int p = 0; p < 4; p++) {
            int n4 = bnq + 8 * p;
            rb[p] = *reinterpret_cast<const float4*>(WT + (size_t)(kb + bk) * CC + n4 * 4);
        }
    };
    auto sts_chunk = [&]() {
#pragma unroll
        for (int p = 0; p < 2; p++) {
            int r = ar + p * 32;
            As[akq * 4 + 0][r] = ra[p].x;
            As[akq * 4 + 1][r] = ra[p].y;
            As[akq * 4 + 2][r] = ra[p].z;
            As[akq * 4 + 3][r] = ra[p].w;
        }
#pragma unroll
        for (int p = 0; p < 4; p++) {
            int n4 = bnq + 8 * p;
            *reinterpret_cast<float4*>(&Bs[bk][n4 * 4]) = rb[p];
        }
    };

    ldg_chunk(0);
    sts_chunk();
    __syncthreads();

#pragma unroll
    for (int c = 0; c < 4; c++) {
        if (c < 3) ldg_chunk((c + 1) * 32);   // prefetch next chunk into regs
#pragma unroll
        for (int k = 0; k < 32; k++) {
            float4 av = *reinterpret_cast<float4*>(&As[k][ty * 4]);
            float4 b0 = *reinterpret_cast<float4*>(&Bs[k][tx * 8]);
            float4 b1 = *reinterpret_cast<float4*>(&Bs[k][tx * 8 + 4]);
            float a[4] = {av.x, av.y, av.z, av.w};
            float b[8] = {b0.x, b0.y, b0.z, b0.w, b1.x, b1.y, b1.z, b1.w};
#pragma unroll
            for (int i = 0; i < 4; i++)
#pragma unroll
                for (int j = 0; j < 8; j++) acc[i][j] += a[i] * b[j];
        }
        if (c < 3) {
            __syncthreads();   // everyone done reading the tile
            sts_chunk();
            __syncthreads();   // new tile visible
        }
    }

    // ---- epilogue: float4 stores ----
#pragma unroll
    for (int i = 0; i < 4; i++) {
        int gm = row0 + ty * 4 + i;
        if (gm < M) {
            float v0[4], v1[4];
#pragma unroll
            for (int j = 0; j < 4; j++) {
                float v = acc[i][j] + bias_r[j];
                v0[j] = RELU ? fmaxf(v, 0.f) : v;
            }
#pragma unroll
            for (int j = 0; j < 4; j++) {
                float v = acc[i][4 + j] + bias_r[4 + j];
                v1[j] = RELU ? fmaxf(v, 0.f) : v;
            }
            float4* o = reinterpret_cast<float4*>(out + (size_t)gm * CC + tx * 8);
            o[0] = make_float4(v0[0], v0[1], v0[2], v0[3]);
            o[1] = make_float4(v1[0], v1[1], v1[2], v1[3]);
        }
    }
}

// ---- finalize: out = relu(out / max(cnt_n, 1)) ----
__global__ void finalize_kernel(float* __restrict__ out) {
    int i = blockIdx.x * blockDim.x + threadIdx.x;
    int stride = gridDim.x * blockDim.x;
    float4* p = reinterpret_cast<float4*>(out);
    for (; i < NN * CC / 4; i += stride) {
        int m = i >> 5;  // 32 float4 per row
        float s = 1.f / fmaxf(g_cnt_n[m], 1.f);
        float4 v = p[i];
        v.x = fmaxf(v.x * s, 0.f);
        v.y = fmaxf(v.y * s, 0.f);
        v.z = fmaxf(v.z * s, 0.f);
        v.w = fmaxf(v.w * s, 0.f);
        p[i] = v;
    }
}

extern "C" void kernel_launch(void* const* d_in, const int* in_sizes, int n_in,
                              void* d_out, int out_size) {
    const float* x  = (const float*)d_in[0];
    const int*   hi = (const int*)d_in[1];
    const float* W1 = (const float*)d_in[2];
    const float* b1 = (const float*)d_in[3];
    const float* W2 = (const float*)d_in[4];
    const float* b2 = (const float*)d_in[5];
    float* out = (float*)d_out;

    int ninc = in_sizes[1] / 2;
    const int* nidx = hi;          // hyperedge_index[0]
    const int* eidx = hi + ninc;   // hyperedge_index[1]

    prep_kernel<<<1024, 256>>>(out, W1, W2);
    scatter1_kernel<<<(ninc + 7) / 8, 256>>>(x, nidx, eidx, ninc);
    gemm_kernel<0><<<(NE + 63) / 64, 256>>>(b1);
    gemm_kernel<1><<<(NE + 63) / 64, 256>>>(b2);
    scatter2_kernel<<<(ninc + 7) / 8, 256>>>(nidx, eidx, out, ninc);
    finalize_kernel<<<1024, 256>>>(out);
}